// round 15
// baseline (speedup 1.0000x reference)
#include <cuda_runtime.h>
#include <cuda_bf16.h>

// SqRL fused, single launch (R11 base: IMGS=4, fully-unrolled hot path,
// warp-coherent broadcast fast path, default store policy) + fine-grained
// role interleave: every 3rd blockIdx.x slot is a V (transpose) tile, the
// rest are H tasks. Keeps the DRAM read/write mix uniform in time to cut
// HBM bus-turnaround losses (previously all-H then all-V per image group).
//
// Ring r (0..255), i = 255-r, el = 2r+1, b1 = 256+r:
//   b2 = 766-r, b3 = 767+r (right edge, vertical)
//   b4 = 1277-r, b5 = 1278+r (bottom edge)
//   b6 = 1788-r, b7 = 1789+r (left edge, vertical)
// Vertical identities (role V):
//   out[r][511+row]  = x[row][256+r]  (|row-255| <= r)
//   out[r][2044-row] = x[row][255-r]  (|row-256| <= r)

#define HH    512
#define HR    256
#define RL    2048
#define IMGS  4

__global__ __launch_bounds__(256)
void sqrl_main(const float* __restrict__ x, float* __restrict__ out, int images) {
    const int t   = threadIdx.x;
    const int bc0 = blockIdx.y * IMGS;
    const size_t istep = (size_t)HH * HH;
    const size_t ostep = (size_t)HR * RL;
    const bool full = (bc0 + IMGS <= images);
    const int nim = full ? IMGS : (images - bc0);

    // Role interleave: x % 3 == 2 -> V tile (x/3), else H task 2*(x/3)+(x%3).
    const int xi = blockIdx.x;
    const int xq = xi / 3;
    const int xm = xi - 3 * xq;

    if (xm != 2) {
        // ─── Role H: one (ring, half-row) x IMGS images ───
        const int h  = 2 * xq + xm;      // 0..511
        const int r  = h >> 1;
        const int jb = h & 1;
        const int i  = (HR - 1) - r;
        const int el = 2 * r + 1;
        const int b1 = i + el;
        const int b2 = b1 + 2 * i;
        const int b3 = b2 + el;
        const int b4 = b3 + 2 * i;
        const int b5 = b4 + el;
        const int b6 = b5 + 2 * i;
        const int b7 = b6 + el;

        int idv[4];
        const int base = jb * 1024 + t * 4;
        #pragma unroll
        for (int k = 0; k < 4; ++k) {
            const int j  = base + k;
            const int jp = (j >= 2044) ? j - 2044 : j;   // tail wrap
            int v;
            if (jp < i)        v = i * HH + i;                   // TL corner
            else if (jp < b1)  v = i * HH + jp;                  // top edge
            else if (jp < b2)  v = i * HH + (HH - 1 - i);        // TR corner
            else if (jp < b3)  v = -1;                           // right edge -> V
            else if (jp < b4)  v = b1 * HH + b1;                 // BR corner
            else if (jp < b5)  v = b1 * HH + (b1 - (jp - b4));   // bottom edge (rev)
            else if (jp < b6)  v = b1 * HH + i;                  // BL corner
            else if (jp < b7)  v = -1;                           // left edge -> V
            else               v = i * HH + i;                   // trailing TL corner
            idv[k] = v;
        }

        const int mn = min(min(idv[0], idv[1]), min(idv[2], idv[3]));
        const int mx = max(max(idv[0], idv[1]), max(idv[2], idv[3]));
        if (mx < 0) return;   // fully vertical 4-block: role V owns it

        const float* __restrict__ img  = x + (size_t)bc0 * istep;
        float* __restrict__       orow = out + ((size_t)bc0 * HR + (size_t)r) * RL + base;

        if (mn < 0) {
            // mixed block straddling a vertical-segment boundary (rare)
            for (int kk = 0; kk < nim; ++kk) {
                if (idv[0] >= 0) orow[0] = __ldg(img + idv[0]);
                if (idv[1] >= 0) orow[1] = __ldg(img + idv[1]);
                if (idv[2] >= 0) orow[2] = __ldg(img + idv[2]);
                if (idv[3] >= 0) orow[3] = __ldg(img + idv[3]);
                img += istep; orow += ostep;
            }
        } else if (full) {
            if (mn == mx) {
                // corner-run interior (~50% of H threads): 1 broadcast load per
                // image + splat store. Warp-coherent except at run boundaries.
                float c0 = __ldg(img + idv[0]);
                float c1 = __ldg(img + istep + idv[0]);
                float c2 = __ldg(img + 2 * istep + idv[0]);
                float c3 = __ldg(img + 3 * istep + idv[0]);
                *reinterpret_cast<float4*>(orow)             = make_float4(c0, c0, c0, c0);
                *reinterpret_cast<float4*>(orow + ostep)     = make_float4(c1, c1, c1, c1);
                *reinterpret_cast<float4*>(orow + 2 * ostep) = make_float4(c2, c2, c2, c2);
                *reinterpret_cast<float4*>(orow + 3 * ostep) = make_float4(c3, c3, c3, c3);
            } else {
                // edges / boundary blocks: issue ALL 16 loads, then 4 stores
                float4 v0, v1, v2, v3;
                v0.x = __ldg(img + idv[0]);              v0.y = __ldg(img + idv[1]);
                v0.z = __ldg(img + idv[2]);              v0.w = __ldg(img + idv[3]);
                v1.x = __ldg(img + istep + idv[0]);      v1.y = __ldg(img + istep + idv[1]);
                v1.z = __ldg(img + istep + idv[2]);      v1.w = __ldg(img + istep + idv[3]);
                v2.x = __ldg(img + 2 * istep + idv[0]);  v2.y = __ldg(img + 2 * istep + idv[1]);
                v2.z = __ldg(img + 2 * istep + idv[2]);  v2.w = __ldg(img + 2 * istep + idv[3]);
                v3.x = __ldg(img + 3 * istep + idv[0]);  v3.y = __ldg(img + 3 * istep + idv[1]);
                v3.z = __ldg(img + 3 * istep + idv[2]);  v3.w = __ldg(img + 3 * istep + idv[3]);
                *reinterpret_cast<float4*>(orow)             = v0;
                *reinterpret_cast<float4*>(orow + ostep)     = v1;
                *reinterpret_cast<float4*>(orow + 2 * ostep) = v2;
                *reinterpret_cast<float4*>(orow + 3 * ostep) = v3;
            }
        } else {
            for (int kk = 0; kk < nim; ++kk) {
                const float4 v = make_float4(__ldg(img + idv[0]), __ldg(img + idv[1]),
                                             __ldg(img + idv[2]), __ldg(img + idv[3]));
                *reinterpret_cast<float4*>(orow) = v;
                img += istep; orow += ostep;
            }
        }
    } else {
        // ─── Role V: masked 32x32 transpose, software-pipelined over images ───
        const int v  = xq;                    // 0..255
        const int R0 = (v >> 4) * 32;
        const int C0 = (v & 15) * 32;

        if (C0 >= 256) {
            const int rmax = C0 - 256 + 31;
            if (R0 + 31 < 255 - rmax || R0 > 255 + rmax) return;
        } else {
            const int rmax = 255 - C0;
            if (R0 + 31 < 256 - rmax || R0 > 256 + rmax) return;
        }

        __shared__ float tile[32][33];
        const int tx  = t & 31;
        const int ty  = t >> 5;
        const int row = R0 + tx;

        // prefetch image 0
        float rv[4];
        {
            const float* __restrict__ im = x + (size_t)bc0 * istep;
            #pragma unroll
            for (int k = 0; k < 4; ++k)
                rv[k] = __ldg(im + (size_t)(R0 + ty * 4 + k) * HH + C0 + tx);
        }

        for (int kk = 0; kk < nim; ++kk) {
            #pragma unroll
            for (int k = 0; k < 4; ++k)
                tile[ty * 4 + k][tx] = rv[k];
            __syncthreads();

            float w[4];
            #pragma unroll
            for (int k = 0; k < 4; ++k)
                w[k] = tile[tx][ty * 4 + k];

            // next image's loads fly across the store phase (latency overlap)
            if (kk + 1 < nim) {
                const float* __restrict__ im = x + (size_t)(bc0 + kk + 1) * istep;
                #pragma unroll
                for (int k = 0; k < 4; ++k)
                    rv[k] = __ldg(im + (size_t)(R0 + ty * 4 + k) * HH + C0 + tx);
            }

            float* __restrict__ obase = out + (size_t)(bc0 + kk) * ostep;
            #pragma unroll
            for (int k = 0; k < 4; ++k) {
                const int u = ty * 4 + k;
                if (C0 >= 256) {
                    const int rr = C0 + u - 256;            // right edge ring
                    if (row >= 255 - rr && row <= 255 + rr)
                        obase[(size_t)rr * RL + 511 + row] = w[k];
                } else {
                    const int rr = 255 - (C0 + u);          // left edge ring
                    if (row >= 256 - rr && row <= 256 + rr)
                        obase[(size_t)rr * RL + 2044 - row] = w[k];
                }
            }
            __syncthreads();
        }
    }
}

extern "C" void kernel_launch(void* const* d_in, const int* in_sizes, int n_in,
                              void* d_out, int out_size) {
    const float* x = (const float*)d_in[0];
    float* out = (float*)d_out;
    const int images = in_sizes[0] / (HH * HH);          // 512
    const int groups = (images + IMGS - 1) / IMGS;       // 128

    dim3 grid(2 * HR + 256, groups);   // 768 interleaved H/V slots x 128 groups
    sqrl_main<<<grid, 256>>>(x, out, images);
}

// round 16
// speedup vs baseline: 1.0779x; 1.0779x over previous
#include <cuda_runtime.h>
#include <cuda_bf16.h>

// SqRL fused, single launch (R11 base: IMGS=4, fully-unrolled hot path,
// warp-coherent broadcast fast path, default store policy) + fine-grained
// H/V role interleave (every 3rd x-slot is a V transpose tile) to keep the
// DRAM read/write mix uniform in time, + __launch_bounds__(256, 8) to pin
// regs at 32 so occupancy stays at the validated ~80% (R15 showed the
// interleave restructure alone bloats regs to 40 and masks the effect).
//
// Ring r (0..255), i = 255-r, el = 2r+1, b1 = 256+r:
//   b2 = 766-r, b3 = 767+r (right edge, vertical)
//   b4 = 1277-r, b5 = 1278+r (bottom edge)
//   b6 = 1788-r, b7 = 1789+r (left edge, vertical)
// Vertical identities (role V):
//   out[r][511+row]  = x[row][256+r]  (|row-255| <= r)
//   out[r][2044-row] = x[row][255-r]  (|row-256| <= r)

#define HH    512
#define HR    256
#define RL    2048
#define IMGS  4

__global__ __launch_bounds__(256, 8)
void sqrl_main(const float* __restrict__ x, float* __restrict__ out, int images) {
    const int t   = threadIdx.x;
    const int bc0 = blockIdx.y * IMGS;
    const size_t istep = (size_t)HH * HH;
    const size_t ostep = (size_t)HR * RL;
    const bool full = (bc0 + IMGS <= images);
    const int nim = full ? IMGS : (images - bc0);

    // Role interleave: x % 3 == 2 -> V tile (x/3), else H task 2*(x/3)+(x%3).
    const int xi = blockIdx.x;
    const int xq = xi / 3;
    const int xm = xi - 3 * xq;

    if (xm != 2) {
        // ─── Role H: one (ring, half-row) x IMGS images ───
        const int h  = 2 * xq + xm;      // 0..511
        const int r  = h >> 1;
        const int jb = h & 1;
        const int i  = (HR - 1) - r;
        const int el = 2 * r + 1;
        const int b1 = i + el;
        const int b2 = b1 + 2 * i;
        const int b3 = b2 + el;
        const int b4 = b3 + 2 * i;
        const int b5 = b4 + el;
        const int b6 = b5 + 2 * i;
        const int b7 = b6 + el;

        int idv[4];
        const int base = jb * 1024 + t * 4;
        #pragma unroll
        for (int k = 0; k < 4; ++k) {
            const int j  = base + k;
            const int jp = (j >= 2044) ? j - 2044 : j;   // tail wrap
            int v;
            if (jp < i)        v = i * HH + i;                   // TL corner
            else if (jp < b1)  v = i * HH + jp;                  // top edge
            else if (jp < b2)  v = i * HH + (HH - 1 - i);        // TR corner
            else if (jp < b3)  v = -1;                           // right edge -> V
            else if (jp < b4)  v = b1 * HH + b1;                 // BR corner
            else if (jp < b5)  v = b1 * HH + (b1 - (jp - b4));   // bottom edge (rev)
            else if (jp < b6)  v = b1 * HH + i;                  // BL corner
            else if (jp < b7)  v = -1;                           // left edge -> V
            else               v = i * HH + i;                   // trailing TL corner
            idv[k] = v;
        }

        const int mn = min(min(idv[0], idv[1]), min(idv[2], idv[3]));
        const int mx = max(max(idv[0], idv[1]), max(idv[2], idv[3]));
        if (mx < 0) return;   // fully vertical 4-block: role V owns it

        const float* __restrict__ img  = x + (size_t)bc0 * istep;
        float* __restrict__       orow = out + ((size_t)bc0 * HR + (size_t)r) * RL + base;

        if (mn < 0) {
            // mixed block straddling a vertical-segment boundary (rare)
            for (int kk = 0; kk < nim; ++kk) {
                if (idv[0] >= 0) orow[0] = __ldg(img + idv[0]);
                if (idv[1] >= 0) orow[1] = __ldg(img + idv[1]);
                if (idv[2] >= 0) orow[2] = __ldg(img + idv[2]);
                if (idv[3] >= 0) orow[3] = __ldg(img + idv[3]);
                img += istep; orow += ostep;
            }
        } else if (full) {
            if (mn == mx) {
                // corner-run interior (~50% of H threads): 1 broadcast load per
                // image + splat store. Warp-coherent except at run boundaries.
                float c0 = __ldg(img + idv[0]);
                float c1 = __ldg(img + istep + idv[0]);
                float c2 = __ldg(img + 2 * istep + idv[0]);
                float c3 = __ldg(img + 3 * istep + idv[0]);
                *reinterpret_cast<float4*>(orow)             = make_float4(c0, c0, c0, c0);
                *reinterpret_cast<float4*>(orow + ostep)     = make_float4(c1, c1, c1, c1);
                *reinterpret_cast<float4*>(orow + 2 * ostep) = make_float4(c2, c2, c2, c2);
                *reinterpret_cast<float4*>(orow + 3 * ostep) = make_float4(c3, c3, c3, c3);
            } else {
                // edges / boundary blocks: issue ALL 16 loads, then 4 stores
                float4 v0, v1, v2, v3;
                v0.x = __ldg(img + idv[0]);              v0.y = __ldg(img + idv[1]);
                v0.z = __ldg(img + idv[2]);              v0.w = __ldg(img + idv[3]);
                v1.x = __ldg(img + istep + idv[0]);      v1.y = __ldg(img + istep + idv[1]);
                v1.z = __ldg(img + istep + idv[2]);      v1.w = __ldg(img + istep + idv[3]);
                v2.x = __ldg(img + 2 * istep + idv[0]);  v2.y = __ldg(img + 2 * istep + idv[1]);
                v2.z = __ldg(img + 2 * istep + idv[2]);  v2.w = __ldg(img + 2 * istep + idv[3]);
                v3.x = __ldg(img + 3 * istep + idv[0]);  v3.y = __ldg(img + 3 * istep + idv[1]);
                v3.z = __ldg(img + 3 * istep + idv[2]);  v3.w = __ldg(img + 3 * istep + idv[3]);
                *reinterpret_cast<float4*>(orow)             = v0;
                *reinterpret_cast<float4*>(orow + ostep)     = v1;
                *reinterpret_cast<float4*>(orow + 2 * ostep) = v2;
                *reinterpret_cast<float4*>(orow + 3 * ostep) = v3;
            }
        } else {
            for (int kk = 0; kk < nim; ++kk) {
                const float4 v = make_float4(__ldg(img + idv[0]), __ldg(img + idv[1]),
                                             __ldg(img + idv[2]), __ldg(img + idv[3]));
                *reinterpret_cast<float4*>(orow) = v;
                img += istep; orow += ostep;
            }
        }
    } else {
        // ─── Role V: masked 32x32 transpose, software-pipelined over images ───
        const int v  = xq;                    // 0..255
        const int R0 = (v >> 4) * 32;
        const int C0 = (v & 15) * 32;

        if (C0 >= 256) {
            const int rmax = C0 - 256 + 31;
            if (R0 + 31 < 255 - rmax || R0 > 255 + rmax) return;
        } else {
            const int rmax = 255 - C0;
            if (R0 + 31 < 256 - rmax || R0 > 256 + rmax) return;
        }

        __shared__ float tile[32][33];
        const int tx  = t & 31;
        const int ty  = t >> 5;
        const int row = R0 + tx;

        // prefetch image 0
        float rv[4];
        {
            const float* __restrict__ im = x + (size_t)bc0 * istep;
            #pragma unroll
            for (int k = 0; k < 4; ++k)
                rv[k] = __ldg(im + (size_t)(R0 + ty * 4 + k) * HH + C0 + tx);
        }

        for (int kk = 0; kk < nim; ++kk) {
            #pragma unroll
            for (int k = 0; k < 4; ++k)
                tile[ty * 4 + k][tx] = rv[k];
            __syncthreads();

            float w[4];
            #pragma unroll
            for (int k = 0; k < 4; ++k)
                w[k] = tile[tx][ty * 4 + k];

            // next image's loads fly across the store phase (latency overlap)
            if (kk + 1 < nim) {
                const float* __restrict__ im = x + (size_t)(bc0 + kk + 1) * istep;
                #pragma unroll
                for (int k = 0; k < 4; ++k)
                    rv[k] = __ldg(im + (size_t)(R0 + ty * 4 + k) * HH + C0 + tx);
            }

            float* __restrict__ obase = out + (size_t)(bc0 + kk) * ostep;
            #pragma unroll
            for (int k = 0; k < 4; ++k) {
                const int u = ty * 4 + k;
                if (C0 >= 256) {
                    const int rr = C0 + u - 256;            // right edge ring
                    if (row >= 255 - rr && row <= 255 + rr)
                        obase[(size_t)rr * RL + 511 + row] = w[k];
                } else {
                    const int rr = 255 - (C0 + u);          // left edge ring
                    if (row >= 256 - rr && row <= 256 + rr)
                        obase[(size_t)rr * RL + 2044 - row] = w[k];
                }
            }
            __syncthreads();
        }
    }
}

extern "C" void kernel_launch(void* const* d_in, const int* in_sizes, int n_in,
                              void* d_out, int out_size) {
    const float* x = (const float*)d_in[0];
    float* out = (float*)d_out;
    const int images = in_sizes[0] / (HH * HH);          // 512
    const int groups = (images + IMGS - 1) / IMGS;       // 128

    dim3 grid(2 * HR + 256, groups);   // 768 interleaved H/V slots x 128 groups
    sqrl_main<<<grid, 256>>>(x, out, images);
}